// round 4
// baseline (speedup 1.0000x reference)
#include <cuda_runtime.h>
#include <cstdint>
#include <cstddef>

#define NB_ROWS 2048
#define NCOMBO  64
#define NSTRUCT 512
#define NHID    1024
#define NITER   60
#define PADNNZ  (NCOMBO * NSTRUCT + 2048)
#define SMNNZ   8192

// ---------------- device scratch (static, allocation-free) ----------------
__device__ float g_C1[NB_ROWS * NHID];
__device__ float g_C2[NB_ROWS * NHID];
__device__ float g_Z [NB_ROWS * NSTRUCT];
__device__ int            g_row_ptr[NCOMBO + 1];    // padded offsets (x4)
__device__ __align__(16) unsigned short g_csr_cols[PADNNZ]; // sentinel 512
__device__ int            g_col_ptr[NSTRUCT + 1];   // padded offsets (x4)
__device__ __align__(16) unsigned short g_csc_rows[PADNNZ]; // sentinel 64
__device__ float g_tau;

// ---------------- cp.async helpers ---------------------------------------
__device__ __forceinline__ void cp_async16(void* smem, const void* gmem) {
    unsigned s = (unsigned)__cvta_generic_to_shared(smem);
    asm volatile("cp.async.cg.shared.global [%0], [%1], 16;\n" :: "r"(s), "l"(gmem));
}
__device__ __forceinline__ void cp_commit() {
    asm volatile("cp.async.commit_group;\n");
}
template<int N_> __device__ __forceinline__ void cp_wait() {
    asm volatile("cp.async.wait_group %0;\n" :: "n"(N_));
}

// ---------------- prep: padded CSR/CSC of S + power iteration -> g_tau ----
__global__ void prep_kernel(const float* __restrict__ S)
{
    __shared__ unsigned char s8[NCOMBO * NSTRUCT];   // 32KB
    __shared__ float v[NSTRUCT + 1];                 // v[512] = 0 sentinel
    __shared__ float sv[NCOMBO + 1];                 // sv[64] = 0 sentinel
    __shared__ float red[16];
    __shared__ int   scnt[NCOMBO];
    __shared__ int   wtot[16];

    const int t    = threadIdx.x;        // 512 threads
    const int lane = t & 31;
    const int wid  = t >> 5;

    #pragma unroll 4
    for (int i = 0; i < NCOMBO; i++)
        s8[i * NSTRUCT + t] = (S[i * NSTRUCT + t] != 0.0f) ? 1 : 0;
    __syncthreads();

    // ---- CSR (row lists), padded to multiple of 4 with sentinel 512 ----
    if (t < NCOMBO) {
        int c = 0;
        for (int j = 0; j < NSTRUCT; j++) c += s8[t * NSTRUCT + j];
        scnt[t] = c;
    }
    __syncthreads();
    if (t == 0) {
        int acc = 0;
        for (int i = 0; i < NCOMBO; i++) {
            g_row_ptr[i] = acc;
            acc += (scnt[i] + 3) & ~3;
        }
        g_row_ptr[NCOMBO] = acc;
    }
    __syncthreads();
    if (t < NCOMBO) {
        int p = g_row_ptr[t];
        const int e = g_row_ptr[t + 1];
        for (int j = 0; j < NSTRUCT; j++)
            if (s8[t * NSTRUCT + j]) g_csr_cols[p++] = (unsigned short)j;
        while (p < e) g_csr_cols[p++] = (unsigned short)NSTRUCT;
    }

    // ---- CSC (col lists), padded, sentinel 64; block scan over 512 ----
    int cc = 0;
    for (int i = 0; i < NCOMBO; i++) cc += s8[i * NSTRUCT + t];
    const int pc = (cc + 3) & ~3;
    int incl = pc;
    #pragma unroll
    for (int o = 1; o < 32; o <<= 1) {
        int nbr = __shfl_up_sync(0xffffffffu, incl, o);
        if (lane >= o) incl += nbr;
    }
    if (lane == 31) wtot[wid] = incl;
    __syncthreads();
    if (t < 16) {
        int xv = wtot[t];
        #pragma unroll
        for (int o = 1; o < 16; o <<= 1) {
            int nbr = __shfl_up_sync(0x0000ffffu, xv, o);
            if (t >= o) xv += nbr;
        }
        wtot[t] = xv;
    }
    __syncthreads();
    {
        int base = (wid > 0) ? wtot[wid - 1] : 0;
        int cend = base + incl;
        g_col_ptr[t + 1] = cend;
        if (t == 0) g_col_ptr[0] = 0;
        int p = cend - pc;
        for (int i = 0; i < NCOMBO; i++)
            if (s8[i * NSTRUCT + t]) g_csc_rows[p++] = (unsigned short)i;
        while (p < cend) g_csc_rows[p++] = (unsigned short)NCOMBO;
    }
    __syncthreads();

    // ---- power iteration on S^T S + I (sentinels contribute 0) ----
    v[t] = 1.0f / sqrtf((float)NSTRUCT);
    if (t == 0) { v[NSTRUCT] = 0.f; sv[NCOMBO] = 0.f; }
    __syncthreads();
    for (int step = 0; step < 30; step++) {
        if (t < NCOMBO) {
            float a = 0.f;
            const int e = g_row_ptr[t + 1];
            for (int p = g_row_ptr[t]; p < e; p++) a += v[g_csr_cols[p]];
            sv[t] = a;
        }
        __syncthreads();
        float w = v[t];
        {
            const int e = g_col_ptr[t + 1];
            for (int p = g_col_ptr[t]; p < e; p++) w += sv[g_csc_rows[p]];
        }
        float sq = w * w;
        #pragma unroll
        for (int o = 16; o > 0; o >>= 1) sq += __shfl_xor_sync(0xffffffffu, sq, o);
        if (lane == 0) red[wid] = sq;
        __syncthreads();
        if (t == 0) {
            float s = 0.f;
            #pragma unroll
            for (int i = 0; i < 16; i++) s += red[i];
            red[0] = sqrtf(s);
        }
        __syncthreads();
        v[t] = w / red[0];
        __syncthreads();
    }
    if (t < NCOMBO) {
        float a = 0.f;
        const int e = g_row_ptr[t + 1];
        for (int p = g_row_ptr[t]; p < e; p++) a += v[g_csr_cols[p]];
        sv[t] = a;
    }
    __syncthreads();
    {
        float w = v[t];
        const int e = g_col_ptr[t + 1];
        for (int p = g_col_ptr[t]; p < e; p++) w += sv[g_csc_rows[p]];
        float sq = v[t] * w;
        #pragma unroll
        for (int o = 16; o > 0; o >>= 1) sq += __shfl_xor_sync(0xffffffffu, sq, o);
        if (lane == 0) red[wid] = sq;
        __syncthreads();
        if (t == 0) {
            float s = 0.f;
            #pragma unroll
            for (int i = 0; i < 16; i++) s += red[i];
            g_tau = 0.9f / sqrtf(s);
        }
    }
}

// ---------------- fp32 GEMM + bias + relu, cp.async double-buffered ------
template<int BM, int BN, int THREADS, int K, int N>
__device__ __forceinline__ void sgemm_v2(
    const float* __restrict__ A, const float* __restrict__ B,
    const float* __restrict__ bias, float* __restrict__ C)
{
    constexpr int KC = 16;
    constexpr int CA = BM * KC / 4;
    constexpr int CB = KC * BN / 4;
    constexpr int NSTAGE = K / KC;
    __shared__ float As[2][BM][KC];
    __shared__ float Bs[2][KC][BN];

    const int tid = threadIdx.x;
    const int m0  = blockIdx.y * BM;
    const int n0  = blockIdx.x * BN;
    constexpr int TX = BN / 8;
    const int tx = tid % TX;
    const int ty = tid / TX;
    const int rowA = ty * 4;
    const int colA = tx * 4;

    float acc[8][8];
    #pragma unroll
    for (int i = 0; i < 8; i++)
        #pragma unroll
        for (int j = 0; j < 8; j++) acc[i][j] = 0.f;

    {
        #pragma unroll
        for (int c = tid; c < CA; c += THREADS) {
            int m  = c >> 2;
            int kq = (c & 3) * 4;
            cp_async16(&As[0][m][kq], A + (size_t)(m0 + m) * K + kq);
        }
        #pragma unroll
        for (int c = tid; c < CB; c += THREADS) {
            int kr = c / (BN / 4);
            int nq = (c % (BN / 4)) * 4;
            cp_async16(&Bs[0][kr][nq], B + (size_t)kr * N + n0 + nq);
        }
        cp_commit();
    }

    for (int s = 0; s < NSTAGE; s++) {
        if (s + 1 < NSTAGE) {
            const int k0 = (s + 1) * KC;
            const int nb = (s + 1) & 1;
            #pragma unroll
            for (int c = tid; c < CA; c += THREADS) {
                int m  = c >> 2;
                int kq = (c & 3) * 4;
                cp_async16(&As[nb][m][kq], A + (size_t)(m0 + m) * K + k0 + kq);
            }
            #pragma unroll
            for (int c = tid; c < CB; c += THREADS) {
                int kr = c / (BN / 4);
                int nq = (c % (BN / 4)) * 4;
                cp_async16(&Bs[nb][kr][nq], B + (size_t)(k0 + kr) * N + n0 + nq);
            }
            cp_commit();
            cp_wait<1>();
        } else {
            cp_wait<0>();
        }
        __syncthreads();
        const int buf = s & 1;
        #pragma unroll
        for (int kk = 0; kk < KC; kk++) {
            float fa[8], fb[8];
            #pragma unroll
            for (int i = 0; i < 4; i++) {
                fa[i]     = As[buf][rowA + i][kk];
                fa[4 + i] = As[buf][rowA + BM / 2 + i][kk];
            }
            *(float4*)&fb[0] = *(const float4*)&Bs[buf][kk][colA];
            *(float4*)&fb[4] = *(const float4*)&Bs[buf][kk][colA + BN / 2];
            #pragma unroll
            for (int i = 0; i < 8; i++)
                #pragma unroll
                for (int j = 0; j < 8; j++)
                    acc[i][j] = fmaf(fa[i], fb[j], acc[i][j]);
        }
        __syncthreads();
    }

    float4 bl = *(const float4*)(bias + n0 + colA);
    float4 bh = *(const float4*)(bias + n0 + colA + BN / 2);
    #pragma unroll
    for (int half = 0; half < 2; half++) {
        #pragma unroll
        for (int i = 0; i < 4; i++) {
            const int m  = m0 + rowA + half * (BM / 2) + i;
            const int ai = half * 4 + i;
            float4 o;
            o.x = fmaxf(acc[ai][0] + bl.x, 0.f);
            o.y = fmaxf(acc[ai][1] + bl.y, 0.f);
            o.z = fmaxf(acc[ai][2] + bl.z, 0.f);
            o.w = fmaxf(acc[ai][3] + bl.w, 0.f);
            *(float4*)(C + (size_t)m * N + n0 + colA) = o;
            float4 p;
            p.x = fmaxf(acc[ai][4] + bh.x, 0.f);
            p.y = fmaxf(acc[ai][5] + bh.y, 0.f);
            p.z = fmaxf(acc[ai][6] + bh.z, 0.f);
            p.w = fmaxf(acc[ai][7] + bh.w, 0.f);
            *(float4*)(C + (size_t)m * N + n0 + colA + BN / 2) = p;
        }
    }
}

__global__ __launch_bounds__(256, 2) void gemm1_kernel(
    const float* __restrict__ X, const float* __restrict__ W1, const float* __restrict__ b1)
{ sgemm_v2<128, 128, 256, NCOMBO, NHID>(X, W1, b1, g_C1); }

__global__ __launch_bounds__(256, 2) void gemm2_kernel(
    const float* __restrict__ W2, const float* __restrict__ b2)
{ sgemm_v2<128, 128, 256, NHID, NHID>(g_C1, W2, b2, g_C2); }

__global__ __launch_bounds__(128, 2) void gemm3_kernel(
    const float* __restrict__ W3, const float* __restrict__ b3)
{ sgemm_v2<64, 128, 128, NHID, NSTRUCT>(g_C2, W3, b3, g_Z); }

// ---------------- PDHG v4: batch tile = 32 (lane = batch row) -------------
// 64 CTAs x 512 threads (16 warps). Layout s_xbar[j][lane]: every gather has
// a warp-uniform column index -> 32 consecutive floats -> conflict-free.
// Lists padded to x4 with sentinel rows (always 0) for ushort4 index loads.
#define XD (NSTRUCT + 1)   // 513 rows in s_xbar (row 512 = sentinel zeros)
#define YD (NCOMBO + 1)    // 65  rows in s_yhead (row 64 = sentinel zeros)

// dynamic smem partition (bytes)
#define OFF_XBAR   0
#define OFF_YHEAD  (OFF_XBAR + XD * 32 * 4)            // 65664
#define OFF_RED    (OFF_YHEAD + YD * 32 * 4)           // +8320
#define OFF_RP     (OFF_RED + 16 * 32 * 4)             // +2048
#define OFF_CP     (OFF_RP + (NCOMBO + 2) * 4)         // +264
#define OFF_CSR    (OFF_CP + (NSTRUCT + 3) * 4)        // +2060 -> align below
#define OFF_CSR_A  ((OFF_CSR + 15) & ~15)
#define OFF_CSC_A  (OFF_CSR_A + SMNNZ * 2)
#define SMEM_TOTAL (OFF_CSC_A + SMNNZ * 2)

__global__ __launch_bounds__(512, 1) void pdhg_kernel(
    const float* __restrict__ Xg, float* __restrict__ out)
{
    extern __shared__ char smem[];
    float* s_xbar  = (float*)(smem + OFF_XBAR);
    float* s_yhead = (float*)(smem + OFF_YHEAD);
    float* s_red   = (float*)(smem + OFF_RED);
    int*   s_rp    = (int*)  (smem + OFF_RP);
    int*   s_cp    = (int*)  (smem + OFF_CP);
    unsigned short* s_csr = (unsigned short*)(smem + OFF_CSR_A);
    unsigned short* s_csc = (unsigned short*)(smem + OFF_CSC_A);

    const int tid  = threadIdx.x;
    const int lane = tid & 31;       // batch sub-row
    const int wid  = tid >> 5;       // 0..15
    const int brow = blockIdx.x * 32 + lane;

    for (int p = tid; p < NCOMBO + 1;  p += 512) s_rp[p] = g_row_ptr[p];
    for (int p = tid; p < NSTRUCT + 1; p += 512) s_cp[p] = g_col_ptr[p];
    // zero xbar + yhead (incl. sentinel rows)
    for (int p = tid; p < XD * 32; p += 512) s_xbar[p] = 0.f;
    for (int p = tid; p < YD * 32; p += 512) s_yhead[p] = 0.f;
    __syncthreads();
    const int nr = s_rp[NCOMBO];
    const int nc = s_cp[NSTRUCT];
    const bool fits = (nr <= SMNNZ) && (nc <= SMNNZ);
    if (fits) {
        for (int p = tid; p < nr; p += 512) s_csr[p] = g_csr_cols[p];
        for (int p = tid; p < nc; p += 512) s_csc[p] = g_csc_rows[p];
    }
    const ushort4* __restrict__ csr4 =
        fits ? (const ushort4*)s_csr : (const ushort4*)g_csr_cols;
    const ushort4* __restrict__ csc4 =
        fits ? (const ushort4*)s_csc : (const ushort4*)g_csc_rows;
    const float tau = g_tau;

    // per-thread state: 32 x-columns (j = wid*32 + k), 4 head rows (i = wid*4+r)
    float x[32], z[32], yt[32];
    #pragma unroll
    for (int q = 0; q < 8; q++) {
        float4 z4 = *(const float4*)(g_Z + (size_t)brow * NSTRUCT + wid * 32 + q * 4);
        z[q * 4 + 0] = z4.x; z[q * 4 + 1] = z4.y;
        z[q * 4 + 2] = z4.z; z[q * 4 + 3] = z4.w;
    }
    #pragma unroll
    for (int k = 0; k < 32; k++) { x[k] = 0.f; yt[k] = 0.f; }
    float yh[4], Bv[4];
    int rs4[4], re4[4];
    #pragma unroll
    for (int r = 0; r < 4; r++) {
        const int i = wid * 4 + r;
        yh[r] = 0.f;
        Bv[r] = Xg[(size_t)brow * NCOMBO + i];
        rs4[r] = s_rp[i] >> 2;
        re4[r] = s_rp[i + 1] >> 2;
    }
    __syncthreads();

    #pragma unroll 1
    for (int it = 0; it < NITER; it++) {
        // ---- phase A: y-head rows (uniform-index gathers, 4 accumulators) ----
        #pragma unroll
        for (int r = 0; r < 4; r++) {
            float a0 = 0.f, a1 = 0.f, a2 = 0.f, a3 = 0.f;
            const int pe = re4[r];
            for (int p = rs4[r]; p < pe; p++) {
                const ushort4 c = csr4[p];
                a0 += s_xbar[c.x * 32 + lane];
                a1 += s_xbar[c.y * 32 + lane];
                a2 += s_xbar[c.z * 32 + lane];
                a3 += s_xbar[c.w * 32 + lane];
            }
            const float acc = (a0 + a1) + (a2 + a3);
            yh[r] = fmaxf(fmaf(tau, acc - Bv[r], yh[r]), 0.f);
            s_yhead[(wid * 4 + r) * 32 + lane] = yh[r];
        }
        __syncthreads();

        // ---- phase B1: y-tail + KTy + residual d (stashed in s_xbar slot) ----
        float ss = 0.f;
        #pragma unroll
        for (int k = 0; k < 32; k++) {
            const int j = wid * 32 + k;
            const float xb_old = s_xbar[j * 32 + lane];
            yt[k] = fmaxf(fmaf(-tau, xb_old, yt[k]), 0.f);
            float t0 = 0.f, t1 = 0.f, t2 = 0.f, t3 = 0.f;
            const int ps = s_cp[j] >> 2, pe = s_cp[j + 1] >> 2;
            for (int p = ps; p < pe; p++) {
                const ushort4 rr = csc4[p];
                t0 += s_yhead[rr.x * 32 + lane];
                t1 += s_yhead[rr.y * 32 + lane];
                t2 += s_yhead[rr.z * 32 + lane];
                t3 += s_yhead[rr.w * 32 + lane];
            }
            const float tv = ((t0 + t1) + (t2 + t3)) - yt[k];
            const float d  = fmaf(-tau, tv, x[k]) + tau - z[k];
            ss += d * d;
            s_xbar[j * 32 + lane] = d;
        }
        s_red[wid * 32 + lane] = ss;
        __syncthreads();

        // ---- phase B2: norm -> scale -> x / xbar update ----
        float tot = 0.f;
        #pragma unroll
        for (int w = 0; w < 16; w++) tot += s_red[w * 32 + lane];
        const float sc = fmaxf(1.f - tau / fmaxf(sqrtf(tot), 1e-12f), 0.f);
        #pragma unroll
        for (int k = 0; k < 32; k++) {
            const int j = wid * 32 + k;
            const float d  = s_xbar[j * 32 + lane];
            const float xn = fmaf(sc, d, z[k]);
            s_xbar[j * 32 + lane] = 2.f * xn - x[k];
            x[k] = xn;
        }
        __syncthreads();
    }

    // ---- output: per-thread contiguous 128B spans ----
    #pragma unroll
    for (int q = 0; q < 8; q++) {
        float4 o;
        o.x = x[q * 4 + 0]; o.y = x[q * 4 + 1];
        o.z = x[q * 4 + 2]; o.w = x[q * 4 + 3];
        *(float4*)(out + (size_t)brow * NSTRUCT + wid * 32 + q * 4) = o;
    }
}

// ---------------- launch -------------------------------------------------
extern "C" void kernel_launch(void* const* d_in, const int* in_sizes, int n_in,
                              void* d_out, int out_size)
{
    const float* X  = (const float*)d_in[0];
    const float* W1 = (const float*)d_in[1];
    const float* b1 = (const float*)d_in[2];
    const float* W2 = (const float*)d_in[3];
    const float* b2 = (const float*)d_in[4];
    const float* W3 = (const float*)d_in[5];
    const float* b3 = (const float*)d_in[6];
    const float* S  = (const float*)d_in[7];
    float* out = (float*)d_out;

    cudaFuncSetAttribute(pdhg_kernel,
                         cudaFuncAttributeMaxDynamicSharedMemorySize, SMEM_TOTAL);

    prep_kernel<<<1, 512>>>(S);

    gemm1_kernel<<<dim3(NHID / 128,    NB_ROWS / 128), 256>>>(X, W1, b1);
    gemm2_kernel<<<dim3(NHID / 128,    NB_ROWS / 128), 256>>>(W2, b2);
    gemm3_kernel<<<dim3(NSTRUCT / 128, NB_ROWS / 64),  128>>>(W3, b3);

    pdhg_kernel<<<NB_ROWS / 32, 512, SMEM_TOTAL>>>(X, out);
}

// round 5
// speedup vs baseline: 1.0135x; 1.0135x over previous
#include <cuda_runtime.h>
#include <cstdint>
#include <cstddef>

#define NB_ROWS 2048
#define NCOMBO  64
#define NSTRUCT 512
#define NHID    1024
#define NITER   60
#define PADNNZ  (NCOMBO * NSTRUCT + 2048)
#define SMNNZ   8192

// ---------------- device scratch (static, allocation-free) ----------------
__device__ float g_C1[NB_ROWS * NHID];
__device__ float g_C2[NB_ROWS * NHID];
__device__ float g_Z [NB_ROWS * NSTRUCT];
__device__ int            g_row_ptr[NCOMBO + 1];    // padded offsets (x4)
__device__ __align__(16) unsigned short g_csr_cols[PADNNZ]; // sentinel 512
__device__ int            g_col_ptr[NSTRUCT + 1];   // padded offsets (x4)
__device__ __align__(16) unsigned short g_csc_rows[PADNNZ]; // sentinel 64
__device__ float g_tau;

// ---------------- cp.async helpers ---------------------------------------
__device__ __forceinline__ void cp_async16(void* smem, const void* gmem) {
    unsigned s = (unsigned)__cvta_generic_to_shared(smem);
    asm volatile("cp.async.cg.shared.global [%0], [%1], 16;\n" :: "r"(s), "l"(gmem));
}
__device__ __forceinline__ void cp_commit() {
    asm volatile("cp.async.commit_group;\n");
}
template<int N_> __device__ __forceinline__ void cp_wait() {
    asm volatile("cp.async.wait_group %0;\n" :: "n"(N_));
}

// ---------------- prep: padded CSR/CSC of S + power iteration -> g_tau ----
__global__ void prep_kernel(const float* __restrict__ S)
{
    __shared__ unsigned char s8[NCOMBO * NSTRUCT];   // 32KB
    __shared__ float v[NSTRUCT + 1];                 // v[512] = 0 sentinel
    __shared__ float sv[NCOMBO + 1];                 // sv[64] = 0 sentinel
    __shared__ float red[16];
    __shared__ int   scnt[NCOMBO];
    __shared__ int   wtot[16];

    const int t    = threadIdx.x;        // 512 threads
    const int lane = t & 31;
    const int wid  = t >> 5;

    #pragma unroll 4
    for (int i = 0; i < NCOMBO; i++)
        s8[i * NSTRUCT + t] = (S[i * NSTRUCT + t] != 0.0f) ? 1 : 0;
    __syncthreads();

    // ---- CSR (row lists), padded to multiple of 4 with sentinel 512 ----
    if (t < NCOMBO) {
        int c = 0;
        for (int j = 0; j < NSTRUCT; j++) c += s8[t * NSTRUCT + j];
        scnt[t] = c;
    }
    __syncthreads();
    if (t == 0) {
        int acc = 0;
        for (int i = 0; i < NCOMBO; i++) {
            g_row_ptr[i] = acc;
            acc += (scnt[i] + 3) & ~3;
        }
        g_row_ptr[NCOMBO] = acc;
    }
    __syncthreads();
    if (t < NCOMBO) {
        int p = g_row_ptr[t];
        const int e = g_row_ptr[t + 1];
        for (int j = 0; j < NSTRUCT; j++)
            if (s8[t * NSTRUCT + j]) g_csr_cols[p++] = (unsigned short)j;
        while (p < e) g_csr_cols[p++] = (unsigned short)NSTRUCT;
    }

    // ---- CSC (col lists), padded, sentinel 64; block scan over 512 ----
    int cc = 0;
    for (int i = 0; i < NCOMBO; i++) cc += s8[i * NSTRUCT + t];
    const int pc = (cc + 3) & ~3;
    int incl = pc;
    #pragma unroll
    for (int o = 1; o < 32; o <<= 1) {
        int nbr = __shfl_up_sync(0xffffffffu, incl, o);
        if (lane >= o) incl += nbr;
    }
    if (lane == 31) wtot[wid] = incl;
    __syncthreads();
    if (t < 16) {
        int xv = wtot[t];
        #pragma unroll
        for (int o = 1; o < 16; o <<= 1) {
            int nbr = __shfl_up_sync(0x0000ffffu, xv, o);
            if (t >= o) xv += nbr;
        }
        wtot[t] = xv;
    }
    __syncthreads();
    {
        int base = (wid > 0) ? wtot[wid - 1] : 0;
        int cend = base + incl;
        g_col_ptr[t + 1] = cend;
        if (t == 0) g_col_ptr[0] = 0;
        int p = cend - pc;
        for (int i = 0; i < NCOMBO; i++)
            if (s8[i * NSTRUCT + t]) g_csc_rows[p++] = (unsigned short)i;
        while (p < cend) g_csc_rows[p++] = (unsigned short)NCOMBO;
    }
    __syncthreads();

    // ---- power iteration on S^T S + I (sentinels contribute 0) ----
    v[t] = 1.0f / sqrtf((float)NSTRUCT);
    if (t == 0) { v[NSTRUCT] = 0.f; sv[NCOMBO] = 0.f; }
    __syncthreads();
    for (int step = 0; step < 30; step++) {
        if (t < NCOMBO) {
            float a = 0.f;
            const int e = g_row_ptr[t + 1];
            for (int p = g_row_ptr[t]; p < e; p++) a += v[g_csr_cols[p]];
            sv[t] = a;
        }
        __syncthreads();
        float w = v[t];
        {
            const int e = g_col_ptr[t + 1];
            for (int p = g_col_ptr[t]; p < e; p++) w += sv[g_csc_rows[p]];
        }
        float sq = w * w;
        #pragma unroll
        for (int o = 16; o > 0; o >>= 1) sq += __shfl_xor_sync(0xffffffffu, sq, o);
        if (lane == 0) red[wid] = sq;
        __syncthreads();
        if (t == 0) {
            float s = 0.f;
            #pragma unroll
            for (int i = 0; i < 16; i++) s += red[i];
            red[0] = sqrtf(s);
        }
        __syncthreads();
        v[t] = w / red[0];
        __syncthreads();
    }
    if (t < NCOMBO) {
        float a = 0.f;
        const int e = g_row_ptr[t + 1];
        for (int p = g_row_ptr[t]; p < e; p++) a += v[g_csr_cols[p]];
        sv[t] = a;
    }
    __syncthreads();
    {
        float w = v[t];
        const int e = g_col_ptr[t + 1];
        for (int p = g_col_ptr[t]; p < e; p++) w += sv[g_csc_rows[p]];
        float sq = v[t] * w;
        #pragma unroll
        for (int o = 16; o > 0; o >>= 1) sq += __shfl_xor_sync(0xffffffffu, sq, o);
        if (lane == 0) red[wid] = sq;
        __syncthreads();
        if (t == 0) {
            float s = 0.f;
            #pragma unroll
            for (int i = 0; i < 16; i++) s += red[i];
            g_tau = 0.9f / sqrtf(s);
        }
    }
}

// ---------------- fp32 GEMM + bias + relu, cp.async double-buffered ------
template<int BM, int BN, int THREADS, int K, int N>
__device__ __forceinline__ void sgemm_v2(
    const float* __restrict__ A, const float* __restrict__ B,
    const float* __restrict__ bias, float* __restrict__ C)
{
    constexpr int KC = 16;
    constexpr int CA = BM * KC / 4;
    constexpr int CB = KC * BN / 4;
    constexpr int NSTAGE = K / KC;
    __shared__ float As[2][BM][KC];
    __shared__ float Bs[2][KC][BN];

    const int tid = threadIdx.x;
    const int m0  = blockIdx.y * BM;
    const int n0  = blockIdx.x * BN;
    constexpr int TX = BN / 8;
    const int tx = tid % TX;
    const int ty = tid / TX;
    const int rowA = ty * 4;
    const int colA = tx * 4;

    float acc[8][8];
    #pragma unroll
    for (int i = 0; i < 8; i++)
        #pragma unroll
        for (int j = 0; j < 8; j++) acc[i][j] = 0.f;

    {
        #pragma unroll
        for (int c = tid; c < CA; c += THREADS) {
            int m  = c >> 2;
            int kq = (c & 3) * 4;
            cp_async16(&As[0][m][kq], A + (size_t)(m0 + m) * K + kq);
        }
        #pragma unroll
        for (int c = tid; c < CB; c += THREADS) {
            int kr = c / (BN / 4);
            int nq = (c % (BN / 4)) * 4;
            cp_async16(&Bs[0][kr][nq], B + (size_t)kr * N + n0 + nq);
        }
        cp_commit();
    }

    for (int s = 0; s < NSTAGE; s++) {
        if (s + 1 < NSTAGE) {
            const int k0 = (s + 1) * KC;
            const int nb = (s + 1) & 1;
            #pragma unroll
            for (int c = tid; c < CA; c += THREADS) {
                int m  = c >> 2;
                int kq = (c & 3) * 4;
                cp_async16(&As[nb][m][kq], A + (size_t)(m0 + m) * K + k0 + kq);
            }
            #pragma unroll
            for (int c = tid; c < CB; c += THREADS) {
                int kr = c / (BN / 4);
                int nq = (c % (BN / 4)) * 4;
                cp_async16(&Bs[nb][kr][nq], B + (size_t)(k0 + kr) * N + n0 + nq);
            }
            cp_commit();
            cp_wait<1>();
        } else {
            cp_wait<0>();
        }
        __syncthreads();
        const int buf = s & 1;
        #pragma unroll
        for (int kk = 0; kk < KC; kk++) {
            float fa[8], fb[8];
            #pragma unroll
            for (int i = 0; i < 4; i++) {
                fa[i]     = As[buf][rowA + i][kk];
                fa[4 + i] = As[buf][rowA + BM / 2 + i][kk];
            }
            *(float4*)&fb[0] = *(const float4*)&Bs[buf][kk][colA];
            *(float4*)&fb[4] = *(const float4*)&Bs[buf][kk][colA + BN / 2];
            #pragma unroll
            for (int i = 0; i < 8; i++)
                #pragma unroll
                for (int j = 0; j < 8; j++)
                    acc[i][j] = fmaf(fa[i], fb[j], acc[i][j]);
        }
        __syncthreads();
    }

    float4 bl = *(const float4*)(bias + n0 + colA);
    float4 bh = *(const float4*)(bias + n0 + colA + BN / 2);
    #pragma unroll
    for (int half = 0; half < 2; half++) {
        #pragma unroll
        for (int i = 0; i < 4; i++) {
            const int m  = m0 + rowA + half * (BM / 2) + i;
            const int ai = half * 4 + i;
            float4 o;
            o.x = fmaxf(acc[ai][0] + bl.x, 0.f);
            o.y = fmaxf(acc[ai][1] + bl.y, 0.f);
            o.z = fmaxf(acc[ai][2] + bl.z, 0.f);
            o.w = fmaxf(acc[ai][3] + bl.w, 0.f);
            *(float4*)(C + (size_t)m * N + n0 + colA) = o;
            float4 p;
            p.x = fmaxf(acc[ai][4] + bh.x, 0.f);
            p.y = fmaxf(acc[ai][5] + bh.y, 0.f);
            p.z = fmaxf(acc[ai][6] + bh.z, 0.f);
            p.w = fmaxf(acc[ai][7] + bh.w, 0.f);
            *(float4*)(C + (size_t)m * N + n0 + colA + BN / 2) = p;
        }
    }
}

__global__ __launch_bounds__(256, 2) void gemm1_kernel(
    const float* __restrict__ X, const float* __restrict__ W1, const float* __restrict__ b1)
{ sgemm_v2<128, 128, 256, NCOMBO, NHID>(X, W1, b1, g_C1); }

__global__ __launch_bounds__(256, 2) void gemm2_kernel(
    const float* __restrict__ W2, const float* __restrict__ b2)
{ sgemm_v2<128, 128, 256, NHID, NHID>(g_C1, W2, b2, g_C2); }

__global__ __launch_bounds__(128, 2) void gemm3_kernel(
    const float* __restrict__ W3, const float* __restrict__ b3)
{ sgemm_v2<64, 128, 128, NHID, NSTRUCT>(g_C2, W3, b3, g_Z); }

// ---------------- PDHG v4: batch tile = 32 (lane = batch row) -------------
// 64 CTAs x 512 threads (16 warps). Layout s_xbar[j][lane]: every gather has
// a warp-uniform column index -> 32 consecutive floats -> conflict-free.
// Lists padded to x4 with sentinel rows (always 0) for ushort4 index loads.
#define XD (NSTRUCT + 1)   // 513 rows in s_xbar (row 512 = sentinel zeros)
#define YD (NCOMBO + 1)    // 65  rows in s_yhead (row 64 = sentinel zeros)

// dynamic smem partition (bytes)
#define OFF_XBAR   0
#define OFF_YHEAD  (OFF_XBAR + XD * 32 * 4)            // 65664
#define OFF_RED    (OFF_YHEAD + YD * 32 * 4)           // +8320
#define OFF_RP     (OFF_RED + 16 * 32 * 4)             // +2048
#define OFF_CP     (OFF_RP + (NCOMBO + 2) * 4)         // +264
#define OFF_CSR    (OFF_CP + (NSTRUCT + 3) * 4)        // +2060 -> align below
#define OFF_CSR_A  ((OFF_CSR + 15) & ~15)
#define OFF_CSC_A  (OFF_CSR_A + SMNNZ * 2)
#define SMEM_TOTAL (OFF_CSC_A + SMNNZ * 2)

__global__ __launch_bounds__(512, 1) void pdhg_kernel(
    const float* __restrict__ Xg, float* __restrict__ out)
{
    extern __shared__ char smem[];
    float* s_xbar  = (float*)(smem + OFF_XBAR);
    float* s_yhead = (float*)(smem + OFF_YHEAD);
    float* s_red   = (float*)(smem + OFF_RED);
    int*   s_rp    = (int*)  (smem + OFF_RP);
    int*   s_cp    = (int*)  (smem + OFF_CP);
    unsigned short* s_csr = (unsigned short*)(smem + OFF_CSR_A);
    unsigned short* s_csc = (unsigned short*)(smem + OFF_CSC_A);

    const int tid  = threadIdx.x;
    const int lane = tid & 31;       // batch sub-row
    const int wid  = tid >> 5;       // 0..15
    const int brow = blockIdx.x * 32 + lane;

    for (int p = tid; p < NCOMBO + 1;  p += 512) s_rp[p] = g_row_ptr[p];
    for (int p = tid; p < NSTRUCT + 1; p += 512) s_cp[p] = g_col_ptr[p];
    // zero xbar + yhead (incl. sentinel rows)
    for (int p = tid; p < XD * 32; p += 512) s_xbar[p] = 0.f;
    for (int p = tid; p < YD * 32; p += 512) s_yhead[p] = 0.f;
    __syncthreads();
    const int nr = s_rp[NCOMBO];
    const int nc = s_cp[NSTRUCT];
    const bool fits = (nr <= SMNNZ) && (nc <= SMNNZ);
    if (fits) {
        for (int p = tid; p < nr; p += 512) s_csr[p] = g_csr_cols[p];
        for (int p = tid; p < nc; p += 512) s_csc[p] = g_csc_rows[p];
    }
    const ushort4* __restrict__ csr4 =
        fits ? (const ushort4*)s_csr : (const ushort4*)g_csr_cols;
    const ushort4* __restrict__ csc4 =
        fits ? (const ushort4*)s_csc : (const ushort4*)g_csc_rows;
    const float tau = g_tau;

    // per-thread state: 32 x-columns (j = wid*32 + k), 4 head rows (i = wid*4+r)
    float x[32], z[32], yt[32];
    #pragma unroll
    for (int q = 0; q < 8; q++) {
        float4 z4 = *(const float4*)(g_Z + (size_t)brow * NSTRUCT + wid * 32 + q * 4);
        z[q * 4 + 0] = z4.x; z[q * 4 + 1] = z4.y;
        z[q * 4 + 2] = z4.z; z[q * 4 + 3] = z4.w;
    }
    #pragma unroll
    for (int k = 0; k < 32; k++) { x[k] = 0.f; yt[k] = 0.f; }
    float yh[4], Bv[4];
    int rs4[4], re4[4];
    #pragma unroll
    for (int r = 0; r < 4; r++) {
        const int i = wid * 4 + r;
        yh[r] = 0.f;
        Bv[r] = Xg[(size_t)brow * NCOMBO + i];
        rs4[r] = s_rp[i] >> 2;
        re4[r] = s_rp[i + 1] >> 2;
    }
    __syncthreads();

    #pragma unroll 1
    for (int it = 0; it < NITER; it++) {
        // ---- phase A: y-head rows (uniform-index gathers, 4 accumulators) ----
        #pragma unroll
        for (int r = 0; r < 4; r++) {
            float a0 = 0.f, a1 = 0.f, a2 = 0.f, a3 = 0.f;
            const int pe = re4[r];
            for (int p = rs4[r]; p < pe; p++) {
                const ushort4 c = csr4[p];
                a0 += s_xbar[c.x * 32 + lane];
                a1 += s_xbar[c.y * 32 + lane];
                a2 += s_xbar[c.z * 32 + lane];
                a3 += s_xbar[c.w * 32 + lane];
            }
            const float acc = (a0 + a1) + (a2 + a3);
            yh[r] = fmaxf(fmaf(tau, acc - Bv[r], yh[r]), 0.f);
            s_yhead[(wid * 4 + r) * 32 + lane] = yh[r];
        }
        __syncthreads();

        // ---- phase B1: y-tail + KTy + residual d (stashed in s_xbar slot) ----
        float ss = 0.f;
        #pragma unroll
        for (int k = 0; k < 32; k++) {
            const int j = wid * 32 + k;
            const float xb_old = s_xbar[j * 32 + lane];
            yt[k] = fmaxf(fmaf(-tau, xb_old, yt[k]), 0.f);
            float t0 = 0.f, t1 = 0.f, t2 = 0.f, t3 = 0.f;
            const int ps = s_cp[j] >> 2, pe = s_cp[j + 1] >> 2;
            for (int p = ps; p < pe; p++) {
                const ushort4 rr = csc4[p];
                t0 += s_yhead[rr.x * 32 + lane];
                t1 += s_yhead[rr.y * 32 + lane];
                t2 += s_yhead[rr.z * 32 + lane];
                t3 += s_yhead[rr.w * 32 + lane];
            }
            const float tv = ((t0 + t1) + (t2 + t3)) - yt[k];
            const float d  = fmaf(-tau, tv, x[k]) + tau - z[k];
            ss += d * d;
            s_xbar[j * 32 + lane] = d;
        }
        s_red[wid * 32 + lane] = ss;
        __syncthreads();

        // ---- phase B2: norm -> scale -> x / xbar update ----
        float tot = 0.f;
        #pragma unroll
        for (int w = 0; w < 16; w++) tot += s_red[w * 32 + lane];
        const float sc = fmaxf(1.f - tau / fmaxf(sqrtf(tot), 1e-12f), 0.f);
        #pragma unroll
        for (int k = 0; k < 32; k++) {
            const int j = wid * 32 + k;
            const float d  = s_xbar[j * 32 + lane];
            const float xn = fmaf(sc, d, z[k]);
            s_xbar[j * 32 + lane] = 2.f * xn - x[k];
            x[k] = xn;
        }
        __syncthreads();
    }

    // ---- output: per-thread contiguous 128B spans ----
    #pragma unroll
    for (int q = 0; q < 8; q++) {
        float4 o;
        o.x = x[q * 4 + 0]; o.y = x[q * 4 + 1];
        o.z = x[q * 4 + 2]; o.w = x[q * 4 + 3];
        *(float4*)(out + (size_t)brow * NSTRUCT + wid * 32 + q * 4) = o;
    }
}

// ---------------- launch -------------------------------------------------
extern "C" void kernel_launch(void* const* d_in, const int* in_sizes, int n_in,
                              void* d_out, int out_size)
{
    const float* X  = (const float*)d_in[0];
    const float* W1 = (const float*)d_in[1];
    const float* b1 = (const float*)d_in[2];
    const float* W2 = (const float*)d_in[3];
    const float* b2 = (const float*)d_in[4];
    const float* W3 = (const float*)d_in[5];
    const float* b3 = (const float*)d_in[6];
    const float* S  = (const float*)d_in[7];
    float* out = (float*)d_out;

    cudaFuncSetAttribute(pdhg_kernel,
                         cudaFuncAttributeMaxDynamicSharedMemorySize, SMEM_TOTAL);

    prep_kernel<<<1, 512>>>(S);

    gemm1_kernel<<<dim3(NHID / 128,    NB_ROWS / 128), 256>>>(X, W1, b1);
    gemm2_kernel<<<dim3(NHID / 128,    NB_ROWS / 128), 256>>>(W2, b2);
    gemm3_kernel<<<dim3(NSTRUCT / 128, NB_ROWS / 64),  128>>>(W3, b3);

    pdhg_kernel<<<NB_ROWS / 32, 512, SMEM_TOTAL>>>(X, out);
}